// round 5
// baseline (speedup 1.0000x reference)
#include <cuda_runtime.h>
#include <cstdint>

// Problem constants
#define BATCH 128
#define SEQ   512
#define HID   512
#define DIM   1024            // 2*HID
#define MROWS (BATCH*SEQ)     // 65536

// Scratch (no device allocation allowed -> __device__ globals)
__device__ float g_dec[BATCH * DIM];     // dec_feat = s_t @ Ws^T + b   (B, D)
__device__ float g_score[BATCH * SEQ];   // attention logits             (B, S)

// ---------------------------------------------------------------------------
// packed f32x2 helpers (B300: doubles fp32 FMA throughput vs scalar FFMA)
// ---------------------------------------------------------------------------
__device__ __forceinline__ void fma2(unsigned long long& c,
                                     unsigned long long a,
                                     unsigned long long b) {
    asm("fma.rn.f32x2 %0, %1, %2, %3;" : "=l"(c) : "l"(a), "l"(b), "l"(c));
}
__device__ __forceinline__ unsigned long long dup2(float x) {
    unsigned long long r;
    unsigned int u = __float_as_uint(x);
    asm("mov.b64 %0, {%1, %1};" : "=l"(r) : "r"(u));
    return r;
}
__device__ __forceinline__ float lo32(unsigned long long v) {
    return __uint_as_float((unsigned int)v);
}
__device__ __forceinline__ float hi32(unsigned long long v) {
    return __uint_as_float((unsigned int)(v >> 32));
}

// ---------------------------------------------------------------------------
// K1: dec_feat[b,e] = sum_d s_t[b,d] * Ws[e,d] + Ws_b[e]
//     s_t[b,d] = d<512 ? h_dec[b,d] : c_dec[b,d-512]
// grid (8, 128) : blockIdx.x = e-tile of 128, blockIdx.y = b ; 128 threads
// ---------------------------------------------------------------------------
__global__ void dec_feat_kernel(const float* __restrict__ h,
                                const float* __restrict__ c,
                                const float* __restrict__ Ws,
                                const float* __restrict__ Wsb) {
    __shared__ float st[DIM];
    const int b = blockIdx.y;
    const int e = blockIdx.x * 128 + threadIdx.x;

    for (int d = threadIdx.x; d < DIM; d += 128)
        st[d] = (d < HID) ? h[b * HID + d] : c[b * HID + d - HID];
    __syncthreads();

    const float* wrow = Ws + (size_t)e * DIM;
    float acc = Wsb[e];
#pragma unroll 8
    for (int d = 0; d < DIM; d++)
        acc = fmaf(st[d], wrow[d], acc);
    g_dec[b * DIM + e] = acc;
}

// ---------------------------------------------------------------------------
// K2: fused  score[b,s] = sum_e v[e] * tanh( (enc @ Wh^T)[row,e]
//                                            + dec_feat[b,e] + cov[b,s]*wc[e] )
// 137 GFLOP GEMM, fused epilogue (enc_feat never materialized).
// Tile: 128 rows x 128 cols, BK=16, 256 threads, 8x8 microtile as 8x4 f32x2.
// Each block covers ALL 1024 e-columns (8 chunks) -> writes score directly.
// ---------------------------------------------------------------------------
#define BM 128
#define BN 128
#define BK 16

__global__ __launch_bounds__(256)
void score_kernel(const float* __restrict__ enc,
                  const float* __restrict__ Wh,
                  const float* __restrict__ cov,
                  const float* __restrict__ v,
                  const float* __restrict__ wc) {
    __shared__ __align__(16) float As[BK][BM];   // 8 KB, stored [k][m]
    __shared__ __align__(16) float Bs[BK][BN];   // 8 KB, stored [k][n]

    const int tid = threadIdx.x;
    const int tx = tid & 15;          // 16 n-groups
    const int ty = tid >> 4;          // 16 m-groups
    const int row0 = blockIdx.x * BM;

    // rows of a block never cross a batch boundary (128 | 512)
    const int b = row0 >> 9;
    const int sbase = (row0 & 511) + ty * 8;

    // load mapping: 64 rows x 16 cols per pass, two passes
    const int lr = tid >> 2;
    const int lc = (tid & 3) << 2;

    float rowpart[8];
#pragma unroll
    for (int i = 0; i < 8; i++) rowpart[i] = 0.f;

    for (int et = 0; et < 8; ++et) {
        const int n0 = et * BN;

        unsigned long long accp[8][4];
#pragma unroll
        for (int i = 0; i < 8; i++)
#pragma unroll
            for (int j = 0; j < 4; j++) accp[i][j] = 0ull;

        for (int k0 = 0; k0 < DIM; k0 += BK) {
            float4 a0 = *(const float4*)&enc[(size_t)(row0 + lr) * DIM + k0 + lc];
            float4 a1 = *(const float4*)&enc[(size_t)(row0 + lr + 64) * DIM + k0 + lc];
            float4 b0 = *(const float4*)&Wh[(size_t)(n0 + lr) * DIM + k0 + lc];
            float4 b1 = *(const float4*)&Wh[(size_t)(n0 + lr + 64) * DIM + k0 + lc];

            __syncthreads();   // previous tile fully consumed
            As[lc + 0][lr] = a0.x; As[lc + 1][lr] = a0.y;
            As[lc + 2][lr] = a0.z; As[lc + 3][lr] = a0.w;
            As[lc + 0][lr + 64] = a1.x; As[lc + 1][lr + 64] = a1.y;
            As[lc + 2][lr + 64] = a1.z; As[lc + 3][lr + 64] = a1.w;
            Bs[lc + 0][lr] = b0.x; Bs[lc + 1][lr] = b0.y;
            Bs[lc + 2][lr] = b0.z; Bs[lc + 3][lr] = b0.w;
            Bs[lc + 0][lr + 64] = b1.x; Bs[lc + 1][lr + 64] = b1.y;
            Bs[lc + 2][lr + 64] = b1.z; Bs[lc + 3][lr + 64] = b1.w;
            __syncthreads();

#pragma unroll
            for (int k = 0; k < BK; k++) {
                const float4 m0 = *(const float4*)&As[k][ty * 8];
                const float4 m1 = *(const float4*)&As[k][ty * 8 + 4];
                const ulonglong2 nb0 = *(const ulonglong2*)&Bs[k][tx * 8];
                const ulonglong2 nb1 = *(const ulonglong2*)&Bs[k][tx * 8 + 4];
                unsigned long long np[4] = {nb0.x, nb0.y, nb1.x, nb1.y};
                float mv[8] = {m0.x, m0.y, m0.z, m0.w, m1.x, m1.y, m1.z, m1.w};
#pragma unroll
                for (int i = 0; i < 8; i++) {
                    const unsigned long long mm = dup2(mv[i]);
#pragma unroll
                    for (int j = 0; j < 4; j++)
                        fma2(accp[i][j], mm, np[j]);
                }
            }
        }

        // fused epilogue: x = acc + dec + cov*wc ; rowpart += v * tanh(x)
        const int ebase = n0 + tx * 8;
        float dv[8], wcv[8], vv[8];
#pragma unroll
        for (int j = 0; j < 8; j++) {
            dv[j]  = g_dec[b * DIM + ebase + j];
            wcv[j] = wc[ebase + j];
            vv[j]  = v[ebase + j];
        }
#pragma unroll
        for (int i = 0; i < 8; i++) {
            const float cv = cov[b * SEQ + sbase + i];
            float p = 0.f;
#pragma unroll
            for (int j = 0; j < 4; j++) {
                const float x0 = lo32(accp[i][j]) + dv[2 * j]     + cv * wcv[2 * j];
                const float x1 = hi32(accp[i][j]) + dv[2 * j + 1] + cv * wcv[2 * j + 1];
                p += vv[2 * j] * tanhf(x0) + vv[2 * j + 1] * tanhf(x1);
            }
            rowpart[i] += p;
        }
    }

    // reduce rowpart over the 16 tx-lanes (butterfly stays inside 16-lane group)
#pragma unroll
    for (int off = 8; off >= 1; off >>= 1)
#pragma unroll
        for (int i = 0; i < 8; i++)
            rowpart[i] += __shfl_xor_sync(0xffffffffu, rowpart[i], off);

    if (tx == 0) {
#pragma unroll
        for (int i = 0; i < 8; i++)
            g_score[row0 + ty * 8 + i] = rowpart[i];
    }
}

// ---------------------------------------------------------------------------
// K3: masked softmax over S + renormalize; writes aw and new_coverage.
// one block per batch row, 512 threads
// ---------------------------------------------------------------------------
__global__ void softmax_kernel(const float* __restrict__ mask,
                               const float* __restrict__ cov,
                               float* __restrict__ out) {
    __shared__ float red[SEQ];
    const int b = blockIdx.x;
    const int s = threadIdx.x;

    const float sc = g_score[b * SEQ + s];

    red[s] = sc;
    __syncthreads();
    for (int off = 256; off > 0; off >>= 1) {
        if (s < off) red[s] = fmaxf(red[s], red[s + off]);
        __syncthreads();
    }
    const float mx = red[0];
    __syncthreads();

    const float ex = expf(sc - mx);
    red[s] = ex;
    __syncthreads();
    for (int off = 256; off > 0; off >>= 1) {
        if (s < off) red[s] += red[s + off];
        __syncthreads();
    }
    const float sum = red[0];
    __syncthreads();

    const float aw0 = (ex / sum) * mask[b * SEQ + s];
    red[s] = aw0;
    __syncthreads();
    for (int off = 256; off > 0; off >>= 1) {
        if (s < off) red[s] += red[s + off];
        __syncthreads();
    }
    const float sum2 = red[0];

    const float aw = aw0 / sum2;
    // output layout: [context (B*D) | aw (B*S) | new_coverage (B*S)]
    out[BATCH * DIM + b * SEQ + s] = aw;
    out[BATCH * DIM + BATCH * SEQ + b * SEQ + s] = cov[b * SEQ + s] + aw;
}

// ---------------------------------------------------------------------------
// K4: context[b,d] = sum_s aw[b,s] * enc[b,s,d]   (memory-bound, 268 MB stream)
// one block per batch, 1024 threads (thread = d), coalesced enc reads
// ---------------------------------------------------------------------------
__global__ void context_kernel(const float* __restrict__ enc,
                               const float* __restrict__ aw,
                               float* __restrict__ outc) {
    __shared__ float aws[SEQ];
    const int b = blockIdx.x;
    for (int s = threadIdx.x; s < SEQ; s += blockDim.x)
        aws[s] = aw[b * SEQ + s];
    __syncthreads();

    const int d = threadIdx.x;
    const float* ebase = enc + (size_t)b * SEQ * DIM + d;
    float acc = 0.f;
#pragma unroll 8
    for (int s = 0; s < SEQ; s++)
        acc = fmaf(aws[s], ebase[(size_t)s * DIM], acc);
    outc[b * DIM + d] = acc;
}

// ---------------------------------------------------------------------------
extern "C" void kernel_launch(void* const* d_in, const int* in_sizes, int n_in,
                              void* d_out, int out_size) {
    const float* h_dec = (const float*)d_in[0];  // (1,B,H)
    const float* c_dec = (const float*)d_in[1];  // (1,B,H)
    const float* enc   = (const float*)d_in[2];  // (B,S,D)
    const float* mask  = (const float*)d_in[3];  // (B,S)
    const float* cov   = (const float*)d_in[4];  // (B,S)
    const float* Wh    = (const float*)d_in[5];  // (D,D)
    const float* Ws    = (const float*)d_in[6];  // (D,D)
    const float* Wsb   = (const float*)d_in[7];  // (D,)
    const float* v     = (const float*)d_in[8];  // (D,)
    const float* wc    = (const float*)d_in[9];  // (D,)
    float* out = (float*)d_out;

    dec_feat_kernel<<<dim3(8, BATCH), 128>>>(h_dec, c_dec, Ws, Wsb);
    score_kernel<<<MROWS / BM, 256>>>(enc, Wh, cov, v, wc);
    softmax_kernel<<<BATCH, SEQ>>>(mask, cov, out);
    context_kernel<<<BATCH, DIM>>>(enc, out + BATCH * DIM, out);
}

// round 7
// speedup vs baseline: 4.8953x; 4.8953x over previous
#include <cuda_runtime.h>
#include <cuda_bf16.h>
#include <cstdint>

#define BATCH 128
#define SEQ   512
#define HID   512
#define DIM   1024
#define MROWS (BATCH*SEQ)
#define NITER 32
#define NCH   4

// Arch-specific (sm_103a/sm_100a) feature gate: tcgen05 / cp.async.bulk are
// only legal in 'a'-target compilation passes. Other passes get the FFMA2
// fallback under the SAME kernel symbol.
#if defined(__CUDA_ARCH_FEAT_SM103_ALL) || defined(__CUDA_ARCH_FEAT_SM100_ALL) || defined(__CUDA_ARCH_FEAT_SM101_ALL)
#define HAS_TC 1
#else
#define HAS_TC 0
#endif

__device__ float g_dec[BATCH * DIM];
__device__ float g_score[BATCH * SEQ];
__device__ float g_cpart[4 * BATCH * DIM];
// Wh pre-converted: [kb=32][half=2] 64KB blocks; block = 512 n-rows x 128B
// (row = [32 hi bf16 | 32 lo bf16]), SW128-swizzled.
__device__ __align__(1024) unsigned char g_whb[32 * 2 * 65536];

// ---------------------------------------------------------------------------
// generic helpers (legal on all targets)
// ---------------------------------------------------------------------------
__device__ __forceinline__ uint32_t swz(uint32_t o) { return o ^ ((o >> 3) & 0x70); }

__device__ __forceinline__ void f4split(float4 f, unsigned long long& hi8,
                                        unsigned long long& lo8) {
    __nv_bfloat16 h0 = __float2bfloat16_rn(f.x), h1 = __float2bfloat16_rn(f.y),
                  h2 = __float2bfloat16_rn(f.z), h3 = __float2bfloat16_rn(f.w);
    unsigned a0 = (unsigned)__bfloat16_as_ushort(h0) |
                  ((unsigned)__bfloat16_as_ushort(h1) << 16);
    unsigned a1 = (unsigned)__bfloat16_as_ushort(h2) |
                  ((unsigned)__bfloat16_as_ushort(h3) << 16);
    hi8 = (unsigned long long)a0 | ((unsigned long long)a1 << 32);
    __nv_bfloat16 l0 = __float2bfloat16_rn(f.x - __bfloat162float(h0));
    __nv_bfloat16 l1 = __float2bfloat16_rn(f.y - __bfloat162float(h1));
    __nv_bfloat16 l2 = __float2bfloat16_rn(f.z - __bfloat162float(h2));
    __nv_bfloat16 l3 = __float2bfloat16_rn(f.w - __bfloat162float(h3));
    unsigned b0 = (unsigned)__bfloat16_as_ushort(l0) |
                  ((unsigned)__bfloat16_as_ushort(l1) << 16);
    unsigned b1 = (unsigned)__bfloat16_as_ushort(l2) |
                  ((unsigned)__bfloat16_as_ushort(l3) << 16);
    lo8 = (unsigned long long)b0 | ((unsigned long long)b1 << 32);
}
__device__ __forceinline__ float tanh_acc(float x) {
    float t = __expf(-2.0f * fabsf(x));
    return copysignf(__fdividef(1.0f - t, 1.0f + t), x);
}
// packed f32x2 (fallback GEMM) — compiled fine on compute_103 in R2
__device__ __forceinline__ void fma2(unsigned long long& c,
                                     unsigned long long a,
                                     unsigned long long b) {
    asm("fma.rn.f32x2 %0, %1, %2, %3;" : "=l"(c) : "l"(a), "l"(b), "l"(c));
}
__device__ __forceinline__ unsigned long long dup2(float x) {
    unsigned long long r;
    unsigned int u = __float_as_uint(x);
    asm("mov.b64 %0, {%1, %1};" : "=l"(r) : "r"(u));
    return r;
}
__device__ __forceinline__ float lo32(unsigned long long v) {
    return __uint_as_float((unsigned int)v);
}
__device__ __forceinline__ float hi32(unsigned long long v) {
    return __uint_as_float((unsigned int)(v >> 32));
}

#if HAS_TC
// ---------------------------------------------------------------------------
// tcgen05 / mbarrier primitives (only in 'a'-target passes)
// ---------------------------------------------------------------------------
__device__ __forceinline__ uint32_t s2u(const void* p) {
    uint32_t a;
    asm("{ .reg .u64 t; cvta.to.shared.u64 t, %1; cvt.u32.u64 %0, t; }"
        : "=r"(a) : "l"(p));
    return a;
}
__device__ __forceinline__ unsigned long long mkdesc(uint32_t addr) {
    // SW128, version=1 (Blackwell), SBO=64, LBO=1
    return 0x4000404000010000ull | ((unsigned long long)(addr >> 4) & 0x3FFF);
}
#define MBAR_INIT(a, c) \
    asm volatile("mbarrier.init.shared.b64 [%0], %1;" :: "r"(a), "r"(c) : "memory")
#define MBAR_INVAL(a) \
    asm volatile("mbarrier.inval.shared.b64 [%0];" :: "r"(a) : "memory")
#define MBAR_EXPECT(a, b) \
    asm volatile("mbarrier.arrive.expect_tx.shared.b64 _, [%0], %1;" :: "r"(a), "r"(b) : "memory")
#define WAITP(mbar, ph) do {                                                        \
    asm volatile("{\n\t.reg .pred P;\n\t"                                           \
        "WL_%=:\n\t"                                                                \
        "mbarrier.try_wait.parity.acquire.cta.shared::cta.b64 P, [%0], %1, 0x989680;\n\t" \
        "@P bra.uni WD_%=;\n\t"                                                     \
        "bra.uni WL_%=;\n\t"                                                        \
        "WD_%=:\n\t}"                                                               \
        :: "r"(mbar), "r"((unsigned)(ph)) : "memory");                              \
} while (0)
#define TC_ALLOC(sa, n) \
    asm volatile("tcgen05.alloc.cta_group::1.sync.aligned.shared::cta.b32 [%0], %1;" \
                 :: "r"(sa), "r"((unsigned)(n)) : "memory")
#define TC_RELINQ() \
    asm volatile("tcgen05.relinquish_alloc_permit.cta_group::1.sync.aligned;")
#define TC_DEALLOC(t, n) \
    asm volatile("tcgen05.dealloc.cta_group::1.sync.aligned.b32 %0, %1;" :: "r"(t), "r"((unsigned)(n)))
#define TC_COMMIT(mbar) \
    asm volatile("tcgen05.commit.cta_group::1.mbarrier::arrive::one.shared::cluster.b64 [%0];" \
                 :: "r"(mbar) : "memory")
#define TC_WAIT_LD()      asm volatile("tcgen05.wait::ld.sync.aligned;" ::: "memory")
#define TC_FENCE_BEFORE() asm volatile("tcgen05.fence::before_thread_sync;" ::: "memory")
#define TC_FENCE_AFTER()  asm volatile("tcgen05.fence::after_thread_sync;" ::: "memory")
#define TC_LD_X32(r, ta)                                                    \
    asm volatile("tcgen05.ld.sync.aligned.32x32b.x32.b32 "                  \
        "{%0, %1, %2, %3, %4, %5, %6, %7, "                                 \
        " %8, %9, %10, %11, %12, %13, %14, %15, "                           \
        " %16, %17, %18, %19, %20, %21, %22, %23, "                         \
        " %24, %25, %26, %27, %28, %29, %30, %31}, [%32];"                  \
        : "=r"((r)[0]),  "=r"((r)[1]),  "=r"((r)[2]),  "=r"((r)[3]),        \
          "=r"((r)[4]),  "=r"((r)[5]),  "=r"((r)[6]),  "=r"((r)[7]),        \
          "=r"((r)[8]),  "=r"((r)[9]),  "=r"((r)[10]), "=r"((r)[11]),       \
          "=r"((r)[12]), "=r"((r)[13]), "=r"((r)[14]), "=r"((r)[15]),       \
          "=r"((r)[16]), "=r"((r)[17]), "=r"((r)[18]), "=r"((r)[19]),       \
          "=r"((r)[20]), "=r"((r)[21]), "=r"((r)[22]), "=r"((r)[23]),       \
          "=r"((r)[24]), "=r"((r)[25]), "=r"((r)[26]), "=r"((r)[27]),       \
          "=r"((r)[28]), "=r"((r)[29]), "=r"((r)[30]), "=r"((r)[31])        \
        : "r"(ta))

__device__ __forceinline__ void mma_bf16_ss(unsigned d, unsigned long long ad,
                                            unsigned long long bd,
                                            unsigned idesc, bool acc) {
    unsigned e = acc ? 1u : 0u;
    asm volatile("{\n\t.reg .pred p;\n\tsetp.ne.u32 p, %5, 0;\n\t"
        "tcgen05.mma.cta_group::1.kind::f16 [%0], %1, %2, %3, {%4, %4, %4, %4}, p;\n\t}"
        :: "r"(d), "l"(ad), "l"(bd), "r"(idesc), "r"(0u), "r"(e) : "memory");
}
__device__ __forceinline__ void bulkcp(unsigned dst, const void* src,
                                       unsigned bytes, unsigned mbar) {
    asm volatile(
        "cp.async.bulk.shared::cta.global.mbarrier::complete_tx::bytes [%0], [%1], %2, [%3];"
        :: "r"(dst), "l"(src), "r"(bytes), "r"(mbar) : "memory");
}
// idesc kind::f16: dtype F32(1<<4), atype BF16(1<<7), btype BF16(1<<10),
// N=128 (16<<17), M=128 (8<<24)
#define IDESC 0x8200490u
#endif  // HAS_TC

// dynamic smem layout (tc path)
#define SM_TMEMP 0
#define SM_BF0   8
#define SM_BF1   16
#define SM_ED0   24
#define SM_ED1   32
#define SM_SSM   64
#define SM_A0    1024
#define SM_A1    17408
#define SM_B0    33792
#define SM_B1    99328
#define SM_DEC   164864
#define SM_WC    166912
#define SM_V     168960
#define SMEM_DYN 171008

// ---------------------------------------------------------------------------
// convB: Wh fp32 -> pre-tiled, pre-swizzled hi/lo bf16 blocks. grid (32,2)x256
// ---------------------------------------------------------------------------
__global__ void convB_kernel(const float* __restrict__ Wh) {
    const int kb = blockIdx.x, half = blockIdx.y;
    unsigned char* dst = g_whb + (size_t)(kb * 2 + half) * 65536;
    const int rb = threadIdx.x >> 1, hk = threadIdx.x & 1;
    for (int i = 0; i < 4; i++) {
        const int nl = rb + i * 128;
        const int n = half * 512 + nl;
#pragma unroll
        for (int q = 0; q < 4; q++) {
            const int kl = hk * 16 + q * 4;
            float4 f = *(const float4*)&Wh[(size_t)n * DIM + kb * 32 + kl];
            unsigned long long hi8, lo8;
            f4split(f, hi8, lo8);
            uint32_t off = (uint32_t)nl * 128 + 2 * kl;
            *(unsigned long long*)(dst + swz(off)) = hi8;
            *(unsigned long long*)(dst + swz(off + 64)) = lo8;
        }
    }
}

// ---------------------------------------------------------------------------
// K1: dec_feat, 4 batches per block (Ws row reuse). grid (8,32) x 128
// ---------------------------------------------------------------------------
__global__ void dec_feat_kernel(const float* __restrict__ h,
                                const float* __restrict__ c,
                                const float* __restrict__ Ws,
                                const float* __restrict__ Wsb) {
    __shared__ float st[4][DIM];
    const int b0 = blockIdx.y * 4;
    const int e = blockIdx.x * 128 + threadIdx.x;
    for (int d = threadIdx.x; d < DIM; d += 128)
#pragma unroll
        for (int bb = 0; bb < 4; bb++) {
            const int b = b0 + bb;
            st[bb][d] = (d < HID) ? h[b * HID + d] : c[b * HID + d - HID];
        }
    __syncthreads();
    const float* wrow = Ws + (size_t)e * DIM;
    const float bias = Wsb[e];
    float a0 = bias, a1 = bias, a2 = bias, a3 = bias;
#pragma unroll 4
    for (int d = 0; d < DIM; d++) {
        const float w = wrow[d];
        a0 = fmaf(st[0][d], w, a0);
        a1 = fmaf(st[1][d], w, a1);
        a2 = fmaf(st[2][d], w, a2);
        a3 = fmaf(st[3][d], w, a3);
    }
    g_dec[(b0 + 0) * DIM + e] = a0;
    g_dec[(b0 + 1) * DIM + e] = a1;
    g_dec[(b0 + 2) * DIM + e] = a2;
    g_dec[(b0 + 3) * DIM + e] = a3;
}

// ---------------------------------------------------------------------------
// K2: fused score. tcgen05 GEMM on 'a'-targets; FFMA2 GEMM otherwise.
// grid 512 x 256 threads for BOTH variants.
// ---------------------------------------------------------------------------
__global__ __launch_bounds__(256)
void score_kernel(const float* __restrict__ enc,
                  const float* __restrict__ Wh,
                  const float* __restrict__ cov,
                  const float* __restrict__ v,
                  const float* __restrict__ wc) {
#if HAS_TC
    extern __shared__ __align__(1024) char smem[];
    const uint32_t sb = s2u(smem);
    const int tid = threadIdx.x, wid = tid >> 5, lane = tid & 31;
    const int row0 = blockIdx.x * 128;
    const int b = row0 >> 9;

    if (wid == 0) TC_ALLOC(sb + SM_TMEMP, 512);
    if (tid == 0) {
        MBAR_INIT(sb + SM_BF0, 1); MBAR_INIT(sb + SM_BF1, 1);
        MBAR_INIT(sb + SM_ED0, 1); MBAR_INIT(sb + SM_ED1, 1);
    }
    __syncthreads();
    uint32_t tb;
    asm volatile("ld.shared.b32 %0, [%1];" : "=r"(tb) : "r"(sb + SM_TMEMP));

    const int r = tid >> 1, hk = tid & 1;              // A-store mapping
    const float* aptr = enc + (size_t)(row0 + r) * DIM + hk * 16;
    char* Ac[2] = {smem + SM_A0, smem + SM_A1};
    const uint32_t Asm[2] = {sb + SM_A0, sb + SM_A1};
    const uint32_t Bsm[2] = {sb + SM_B0, sb + SM_B1};
    const uint32_t BF[2] = {sb + SM_BF0, sb + SM_BF1};
    const uint32_t ED[2] = {sb + SM_ED0, sb + SM_ED1};
    int edph[2] = {0, 0}, bfph[2] = {0, 0};
    bool pend[2] = {false, false};

    const int sp = wid & 3, hf = wid >> 2;             // epilogue mapping
    const int er = sp * 32 + lane;
    const float covr = cov[b * SEQ + (row0 & 511) + er];
    float scacc = 0.f;

    float* sdec = (float*)(smem + SM_DEC);
    float* swc_ = (float*)(smem + SM_WC);
    float* sv_  = (float*)(smem + SM_V);

    float4 pf[4];
#pragma unroll
    for (int q = 0; q < 4; q++) pf[q] = *(const float4*)(aptr + q * 4);

    int gi = 0;
    for (int pass = 0; pass < 2; ++pass) {
        TC_FENCE_AFTER();
        for (int it = 0; it < NITER; ++it, ++gi) {
            const int p = gi & 1;
            if (pend[p]) { WAITP(ED[p], edph[p]); edph[p] ^= 1; pend[p] = false; }
#pragma unroll
            for (int q = 0; q < 4; q++) {
                unsigned long long hi8, lo8;
                f4split(pf[q], hi8, lo8);
                const uint32_t off = (uint32_t)r * 128 + hk * 32 + q * 8;
                *(unsigned long long*)(Ac[p] + swz(off)) = hi8;
                *(unsigned long long*)(Ac[p] + swz(off + 64)) = lo8;
            }
            if (tid == 0) {
                MBAR_EXPECT(BF[p], 65536u);
                bulkcp(Bsm[p], g_whb + ((size_t)it * 2 + pass) * 65536, 65536u, BF[p]);
            }
            if (gi < 63) {
                const int nit = (it + 1 == NITER) ? 0 : it + 1;
#pragma unroll
                for (int q = 0; q < 4; q++)
                    pf[q] = *(const float4*)(aptr + nit * 32 + q * 4);
            }
            asm volatile("fence.proxy.async.shared::cta;" ::: "memory");
            __syncthreads();
            if (tid == 0) {
                WAITP(BF[p], bfph[p]); bfph[p] ^= 1;
                const unsigned long long adb = mkdesc(Asm[p]);
#pragma unroll
                for (int c = 0; c < NCH; c++) {
                    const unsigned long long bdb = mkdesc(Bsm[p] + c * 16384);
                    const unsigned dtm = tb + c * 128;
#pragma unroll
                    for (int ks = 0; ks < 2; ks++) {
                        const unsigned long long ah = adb + ks * 2, al = ah + 4;
                        const unsigned long long bh = bdb + ks * 2, bl = bh + 4;
                        mma_bf16_ss(dtm, ah, bh, IDESC, !(it == 0 && ks == 0));
                        mma_bf16_ss(dtm, ah, bl, IDESC, true);
                        mma_bf16_ss(dtm, al, bh, IDESC, true);
                    }
                }
                TC_COMMIT(ED[p]);
            }
            pend[p] = true;
        }
        for (int i = tid; i < 512; i += 256) {
            const int e = pass * 512 + i;
            sdec[i] = g_dec[b * DIM + e];
            swc_[i] = wc[e];
            sv_[i] = v[e];
        }
#pragma unroll
        for (int p = 0; p < 2; p++)
            if (pend[p]) { WAITP(ED[p], edph[p]); edph[p] ^= 1; pend[p] = false; }
        TC_FENCE_AFTER();
        __syncthreads();
        for (int c = 0; c < NCH; c++) {
            uint32_t dreg[64];
            TC_LD_X32(dreg, tb + c * 128 + hf * 64);
            TC_LD_X32(dreg + 32, tb + c * 128 + hf * 64 + 32);
            TC_WAIT_LD();
            const int ebl = c * 128 + hf * 64;
#pragma unroll
            for (int j = 0; j < 64; j++) {
                const float x = __uint_as_float(dreg[j]) + sdec[ebl + j] +
                                covr * swc_[ebl + j];
                scacc += sv_[ebl + j] * tanh_acc(x);
            }
        }
        TC_FENCE_BEFORE();
        __syncthreads();
    }

    float* ssm = (float*)(smem + SM_SSM);
    if (hf == 0) ssm[er] = scacc;
    __syncthreads();
    if (hf == 1) g_score[row0 + er] = ssm[er] + scacc;
    __syncthreads();
    if (tid == 0) {
        MBAR_INVAL(sb + SM_BF0); MBAR_INVAL(sb + SM_BF1);
        MBAR_INVAL(sb + SM_ED0); MBAR_INVAL(sb + SM_ED1);
    }
    __syncthreads();
    if (wid == 0) { TC_RELINQ(); TC_DEALLOC(tb, 512); }

#else  // ------------------- FFMA2 fallback (proven R2 path) ----------------
    __shared__ __align__(16) float As[16][128];
    __shared__ __align__(16) float Bs[16][128];

    const int tid = threadIdx.x;
    const int tx = tid & 15;
    const int ty = tid >> 4;
    const int row0 = blockIdx.x * 128;
    const int b = row0 >> 9;
    const int sbase = (row0 & 511) + ty * 8;
    const int lr = tid >> 2;
    const int lc = (tid & 3) << 2;

    float rowpart[8];
#pragma unroll
    for (int i = 0; i < 8; i++) rowpart[i] = 0.f;

    for (int et = 0; et < 8; ++et) {
        const int n0 = et * 128;
        unsigned long long accp[8][4];
#pragma unroll
        for (int i = 0; i < 8; i++)
#pragma unroll
            for (int j = 0; j < 4; j++) accp[i][j] = 0ull;

        for (int k0 = 0; k0 < DIM; k0 += 16) {
            float4 a0 = *(const float4*)&enc[(size_t)(row0 + lr) * DIM + k0 + lc];
            float4 a1 = *(const float4*)&enc[(size_t)(row0 + lr + 64) * DIM + k0 + lc];
            float4 b0 = *(const float4*)&Wh[(size_t)(n0 + lr) * DIM + k0 + lc];
            float4 b1 = *(const float4*)&Wh[(size_t)(n0 + lr + 64) * DIM + k0 + lc];
            __syncthreads();
            As[lc + 0][lr] = a0.x; As[lc + 1][lr] = a0.y;
            As[lc + 2][lr] = a0.z; As[lc + 3][lr] = a0.w;
            As[lc + 0][lr + 64] = a1.x; As[lc + 1][lr + 64] = a1.y;
            As[lc + 2][lr + 64] = a1.z; As[lc + 3][lr + 64] = a1.w;
            Bs[lc + 0][lr] = b0.x; Bs[lc + 1][lr] = b0.y;
            Bs[lc + 2][lr] = b0.z; Bs[lc + 3][lr] = b0.w;
            Bs[lc + 0][lr + 64] = b1.x; Bs[lc + 1][lr + 64] = b1.y;
            Bs[lc + 2][lr + 64] = b1.z; Bs[lc + 3][lr + 64] = b1.w;
            __syncthreads();
#pragma unroll
            for (int k = 0; k < 16; k++) {
                const float4 m0 = *(const float4*)&As[k][ty * 8];
                const float4 m1 = *(const float4*)&As[k][ty * 8 + 4];
                const ulonglong2 nb0 = *(const ulonglong2*)&Bs[k][tx * 8];
                const ulonglong2 nb1 = *(const ulonglong2*)&Bs[k][tx * 8 + 4];
                unsigned long long np[4] = {nb0.x, nb0.y, nb1.x, nb1.y};
                float mv[8] = {m0.x, m0.y, m0.z, m0.w, m1.x, m1.y, m1.z, m1.w};
#pragma unroll
                for (int i = 0; i < 8; i++) {
                    const unsigned long long mm = dup2(mv[i]);
#pragma unroll
                    for (int j = 0; j < 4; j++)
                        fma2(accp[i][j], mm, np[j]);
                }
            }
        }
        const int ebase = n0 + tx * 8;
        float dv[8], wcv[8], vv[8];
#pragma unroll
        for (int j = 0; j < 8; j++) {
            dv[j]  = g_dec[b * DIM + ebase + j];
            wcv[j] = wc[ebase + j];
            vv[j]  = v[ebase + j];
        }
#pragma unroll
        for (int i = 0; i < 8; i++) {
            const float cv = cov[b * SEQ + sbase + i];
            float p = 0.f;
#pragma unroll
            for (int j = 0; j < 4; j++) {
                const float x0 = lo32(accp[i][j]) + dv[2 * j]     + cv * wcv[2 * j];
                const float x1 = hi32(accp[i][j]) + dv[2 * j + 1] + cv * wcv[2 * j + 1];
                p += vv[2 * j] * tanhf(x0) + vv[2 * j + 1] * tanhf(x1);
            }
            rowpart[i] += p;
        }
    }
#pragma unroll
    for (int off = 8; off >= 1; off >>= 1)
#pragma unroll
        for (int i = 0; i < 8; i++)
            rowpart[i] += __shfl_xor_sync(0xffffffffu, rowpart[i], off);
    if (tx == 0) {
#pragma unroll
        for (int i = 0; i < 8; i++)
            g_score[row0 + ty * 8 + i] = rowpart[i];
    }
#endif
}

// ---------------------------------------------------------------------------
// K3: masked softmax + renorm; writes aw and new_coverage
// ---------------------------------------------------------------------------
__global__ void softmax_kernel(const float* __restrict__ mask,
                               const float* __restrict__ cov,
                               float* __restrict__ out) {
    __shared__ float red[SEQ];
    const int b = blockIdx.x, s = threadIdx.x;
    const float sc = g_score[b * SEQ + s];
    red[s] = sc;
    __syncthreads();
    for (int off = 256; off > 0; off >>= 1) {
        if (s < off) red[s] = fmaxf(red[s], red[s + off]);
        __syncthreads();
    }
    const float mx = red[0];
    __syncthreads();
    const float ex = expf(sc - mx);
    red[s] = ex;
    __syncthreads();
    for (int off = 256; off > 0; off >>= 1) {
        if (s < off) red[s] += red[s + off];
        __syncthreads();
    }
    const float sum = red[0];
    __syncthreads();
    const float aw0 = (ex / sum) * mask[b * SEQ + s];
    red[s] = aw0;
    __syncthreads();
    for (int off = 256; off > 0; off >>= 1) {
        if (s < off) red[s] += red[s + off];
        __syncthreads();
    }
    const float aw = aw0 / red[0];
    out[BATCH * DIM + b * SEQ + s] = aw;
    out[BATCH * DIM + BATCH * SEQ + b * SEQ + s] = cov[b * SEQ + s] + aw;
}

// ---------------------------------------------------------------------------
// K4: context split over 4 s-quarters + deterministic combine
// ---------------------------------------------------------------------------
__global__ void context_part_kernel(const float* __restrict__ enc,
                                    const float* __restrict__ aw) {
    __shared__ float aws[128];
    const int q = blockIdx.x, b = blockIdx.y;
    if (threadIdx.x < 128) aws[threadIdx.x] = aw[b * SEQ + q * 128 + threadIdx.x];
    __syncthreads();
    const int d = threadIdx.x;
    const float* ebase = enc + (size_t)b * SEQ * DIM + (size_t)(q * 128) * DIM + d;
    float acc = 0.f;
#pragma unroll 8
    for (int s = 0; s < 128; s++)
        acc = fmaf(aws[s], ebase[(size_t)s * DIM], acc);
    g_cpart[(q * BATCH + b) * DIM + d] = acc;
}
__global__ void context_sum_kernel(float* __restrict__ outc) {
    const int i = blockIdx.x * 256 + threadIdx.x;
    outc[i] = (g_cpart[i] + g_cpart[BATCH * DIM + i]) +
              (g_cpart[2 * BATCH * DIM + i] + g_cpart[3 * BATCH * DIM + i]);
}

// ---------------------------------------------------------------------------
extern "C" void kernel_launch(void* const* d_in, const int* in_sizes, int n_in,
                              void* d_out, int out_size) {
    const float* h_dec = (const float*)d_in[0];
    const float* c_dec = (const float*)d_in[1];
    const float* enc   = (const float*)d_in[2];
    const float* mask  = (const float*)d_in[3];
    const float* cov   = (const float*)d_in[4];
    const float* Wh    = (const float*)d_in[5];
    const float* Ws    = (const float*)d_in[6];
    const float* Wsb   = (const float*)d_in[7];
    const float* v     = (const float*)d_in[8];
    const float* wc    = (const float*)d_in[9];
    float* out = (float*)d_out;

    // Which variant did the runtime load? tc path has no static smem;
    // fallback carries 16KB static As/Bs.
    cudaFuncAttributes fa;
    cudaFuncGetAttributes(&fa, score_kernel);
    const bool tc = (fa.sharedSizeBytes < 8192);
    size_t dyn = 0;
    if (tc) {
        cudaFuncSetAttribute(score_kernel,
                             cudaFuncAttributeMaxDynamicSharedMemorySize, SMEM_DYN);
        dyn = SMEM_DYN;
        convB_kernel<<<dim3(32, 2), 256>>>(Wh);
    }
    dec_feat_kernel<<<dim3(8, 32), 128>>>(h_dec, c_dec, Ws, Wsb);
    score_kernel<<<MROWS / 128, 256, dyn>>>(enc, Wh, cov, v, wc);
    softmax_kernel<<<BATCH, SEQ>>>(mask, cov, out);
    context_part_kernel<<<dim3(4, BATCH), 1024>>>(enc, out + BATCH * DIM);
    context_sum_kernel<<<BATCH * DIM / 256, 256>>>(out);
}

// round 8
// speedup vs baseline: 5.3317x; 1.0892x over previous
#include <cuda_runtime.h>
#include <cuda_bf16.h>
#include <cstdint>

#define BATCH 128
#define SEQ   512
#define HID   512
#define DIM   1024
#define MROWS (BATCH*SEQ)
#define NITER 32
#define NCH   4

// Arch-specific (sm_103a/sm_100a) feature gate: tcgen05 / cp.async.bulk are
// only legal in 'a'-target compilation passes. Other passes get the FFMA2
// fallback under the SAME kernel symbol.
#if defined(__CUDA_ARCH_FEAT_SM103_ALL) || defined(__CUDA_ARCH_FEAT_SM100_ALL) || defined(__CUDA_ARCH_FEAT_SM101_ALL)
#define HAS_TC 1
#else
#define HAS_TC 0
#endif

__device__ float g_dec[BATCH * DIM];
__device__ float g_score[BATCH * SEQ];
__device__ float g_cpart[8 * BATCH * DIM];
// Wh pre-converted: [kb=32][half=2] 64KB blocks; block = 512 n-rows x 128B
// (row = [32 hi bf16 | 32 lo bf16]), SW128-swizzled.
__device__ __align__(1024) unsigned char g_whb[32 * 2 * 65536];

// ---------------------------------------------------------------------------
// generic helpers (legal on all targets)
// ---------------------------------------------------------------------------
__device__ __forceinline__ uint32_t swz(uint32_t o) { return o ^ ((o >> 3) & 0x70); }

__device__ __forceinline__ void f4split(float4 f, unsigned long long& hi8,
                                        unsigned long long& lo8) {
    __nv_bfloat16 h0 = __float2bfloat16_rn(f.x), h1 = __float2bfloat16_rn(f.y),
                  h2 = __float2bfloat16_rn(f.z), h3 = __float2bfloat16_rn(f.w);
    unsigned a0 = (unsigned)__bfloat16_as_ushort(h0) |
                  ((unsigned)__bfloat16_as_ushort(h1) << 16);
    unsigned a1 = (unsigned)__bfloat16_as_ushort(h2) |
                  ((unsigned)__bfloat16_as_ushort(h3) << 16);
    hi8 = (unsigned long long)a0 | ((unsigned long long)a1 << 32);
    __nv_bfloat16 l0 = __float2bfloat16_rn(f.x - __bfloat162float(h0));
    __nv_bfloat16 l1 = __float2bfloat16_rn(f.y - __bfloat162float(h1));
    __nv_bfloat16 l2 = __float2bfloat16_rn(f.z - __bfloat162float(h2));
    __nv_bfloat16 l3 = __float2bfloat16_rn(f.w - __bfloat162float(h3));
    unsigned b0 = (unsigned)__bfloat16_as_ushort(l0) |
                  ((unsigned)__bfloat16_as_ushort(l1) << 16);
    unsigned b1 = (unsigned)__bfloat16_as_ushort(l2) |
                  ((unsigned)__bfloat16_as_ushort(l3) << 16);
    lo8 = (unsigned long long)b0 | ((unsigned long long)b1 << 32);
}
__device__ __forceinline__ float tanh_hw(float x) {
    float r;
    asm("tanh.approx.f32 %0, %1;" : "=f"(r) : "f"(x));
    return r;
}
// packed f32x2 (fallback GEMM)
__device__ __forceinline__ void fma2(unsigned long long& c,
                                     unsigned long long a,
                                     unsigned long long b) {
    asm("fma.rn.f32x2 %0, %1, %2, %3;" : "=l"(c) : "l"(a), "l"(b), "l"(c));
}
__device__ __forceinline__ unsigned long long dup2(float x) {
    unsigned long long r;
    unsigned int u = __float_as_uint(x);
    asm("mov.b64 %0, {%1, %1};" : "=l"(r) : "r"(u));
    return r;
}
__device__ __forceinline__ float lo32(unsigned long long v) {
    return __uint_as_float((unsigned int)v);
}
__device__ __forceinline__ float hi32(unsigned long long v) {
    return __uint_as_float((unsigned int)(v >> 32));
}

#if HAS_TC
// ---------------------------------------------------------------------------
// tcgen05 / mbarrier primitives (only in 'a'-target passes)
// ---------------------------------------------------------------------------
__device__ __forceinline__ uint32_t s2u(const void* p) {
    uint32_t a;
    asm("{ .reg .u64 t; cvta.to.shared.u64 t, %1; cvt.u32.u64 %0, t; }"
        : "=r"(a) : "l"(p));
    return a;
}
__device__ __forceinline__ unsigned long long mkdesc(uint32_t addr) {
    // SW128, version=1 (Blackwell), SBO=64, LBO=1
    return 0x4000404000010000ull | ((unsigned long long)(addr >> 4) & 0x3FFF);
}
#define MBAR_INIT(a, c) \
    asm volatile("mbarrier.init.shared.b64 [%0], %1;" :: "r"(a), "r"(c) : "memory")
#define MBAR_INVAL(a) \
    asm volatile("mbarrier.inval.shared.b64 [%0];" :: "r"(a) : "memory")
#define MBAR_EXPECT(a, b) \
    asm volatile("mbarrier.arrive.expect_tx.shared.b64 _, [%0], %1;" :: "r"(a), "r"(b) : "memory")
#define MBAR_ARRIVE(a) \
    asm volatile("mbarrier.arrive.shared.b64 _, [%0];" :: "r"(a) : "memory")
#define WAITP(mbar, ph) do {                                                        \
    asm volatile("{\n\t.reg .pred P;\n\t"                                           \
        "WL_%=:\n\t"                                                                \
        "mbarrier.try_wait.parity.acquire.cta.shared::cta.b64 P, [%0], %1, 0x989680;\n\t" \
        "@P bra.uni WD_%=;\n\t"                                                     \
        "bra.uni WL_%=;\n\t"                                                        \
        "WD_%=:\n\t}"                                                               \
        :: "r"(mbar), "r"((unsigned)(ph)) : "memory");                              \
} while (0)
#define TC_ALLOC(sa, n) \
    asm volatile("tcgen05.alloc.cta_group::1.sync.aligned.shared::cta.b32 [%0], %1;" \
                 :: "r"(sa), "r"((unsigned)(n)) : "memory")
#define TC_RELINQ() \
    asm volatile("tcgen05.relinquish_alloc_permit.cta_group::1.sync.aligned;")
#define TC_DEALLOC(t, n) \
    asm volatile("tcgen05.dealloc.cta_group::1.sync.aligned.b32 %0, %1;" :: "r"(t), "r"((unsigned)(n)))
#define TC_COMMIT(mbar) \
    asm volatile("tcgen05.commit.cta_group::1.mbarrier::arrive::one.shared::cluster.b64 [%0];" \
                 :: "r"(mbar) : "memory")
#define TC_WAIT_LD()      asm volatile("tcgen05.wait::ld.sync.aligned;" ::: "memory")
#define TC_FENCE_BEFORE() asm volatile("tcgen05.fence::before_thread_sync;" ::: "memory")
#define TC_FENCE_AFTER()  asm volatile("tcgen05.fence::after_thread_sync;" ::: "memory")
#define TC_LD_X32(r, ta)                                                    \
    asm volatile("tcgen05.ld.sync.aligned.32x32b.x32.b32 "                  \
        "{%0, %1, %2, %3, %4, %5, %6, %7, "                                 \
        " %8, %9, %10, %11, %12, %13, %14, %15, "                           \
        " %16, %17, %18, %19, %20, %21, %22, %23, "                         \
        " %24, %25, %26, %27, %28, %29, %30, %31}, [%32];"                  \
        : "=r"((r)[0]),  "=r"((r)[1]),  "=r"((r)[2]),  "=r"((r)[3]),        \
          "=r"((r)[4]),  "=r"((r)[5]),  "=r"((r)[6]),  "=r"((r)[7]),        \
          "=r"((r)[8]),  "=r"((r)[9]),  "=r"((r)[10]), "=r"((r)[11]),       \
          "=r"((r)[12]), "=r"((r)[13]), "=r"((r)[14]), "=r"((r)[15]),       \
          "=r"((r)[16]), "=r"((r)[17]), "=r"((r)[18]), "=r"((r)[19]),       \
          "=r"((r)[20]), "=r"((r)[21]), "=r"((r)[22]), "=r"((r)[23]),       \
          "=r"((r)[24]), "=r"((r)[25]), "=r"((r)[26]), "=r"((r)[27]),       \
          "=r"((r)[28]), "=r"((r)[29]), "=r"((r)[30]), "=r"((r)[31])        \
        : "r"(ta))

__device__ __forceinline__ void mma_bf16_ss(unsigned d, unsigned long long ad,
                                            unsigned long long bd,
                                            unsigned idesc, bool acc) {
    unsigned e = acc ? 1u : 0u;
    asm volatile("{\n\t.reg .pred p;\n\tsetp.ne.u32 p, %5, 0;\n\t"
        "tcgen05.mma.cta_group::1.kind::f16 [%0], %1, %2, %3, {%4, %4, %4, %4}, p;\n\t}"
        :: "r"(d), "l"(ad), "l"(bd), "r"(idesc), "r"(0u), "r"(e) : "memory");
}
__device__ __forceinline__ void bulkcp(unsigned dst, const void* src,
                                       unsigned bytes, unsigned mbar) {
    asm volatile(
        "cp.async.bulk.shared::cta.global.mbarrier::complete_tx::bytes [%0], [%1], %2, [%3];"
        :: "r"(dst), "l"(src), "r"(bytes), "r"(mbar) : "memory");
}
// idesc kind::f16: dtype F32(1<<4), atype BF16(1<<7), btype BF16(1<<10),
// N=128 (16<<17), M=128 (8<<24)
#define IDESC 0x8200490u
#endif  // HAS_TC

// dynamic smem layout (tc path)
#define SM_TMEMP 0
#define SM_BF0   8
#define SM_BF1   16
#define SM_ED0   24
#define SM_ED1   32
#define SM_AF0   40
#define SM_AF1   48
#define SM_SSM   64
#define SM_A0    1024
#define SM_A1    17408
#define SM_B0    33792
#define SM_B1    99328
#define SM_DEC   164864
#define SM_WC    166912
#define SM_V     168960
#define SMEM_DYN 171008

// ---------------------------------------------------------------------------
// convB: Wh fp32 -> pre-tiled, pre-swizzled hi/lo bf16 blocks. grid (32,2)x256
// ---------------------------------------------------------------------------
__global__ void convB_kernel(const float* __restrict__ Wh) {
    const int kb = blockIdx.x, half = blockIdx.y;
    unsigned char* dst = g_whb + (size_t)(kb * 2 + half) * 65536;
    const int rb = threadIdx.x >> 1, hk = threadIdx.x & 1;
    for (int i = 0; i < 4; i++) {
        const int nl = rb + i * 128;
        const int n = half * 512 + nl;
#pragma unroll
        for (int q = 0; q < 4; q++) {
            const int kl = hk * 16 + q * 4;
            float4 f = *(const float4*)&Wh[(size_t)n * DIM + kb * 32 + kl];
            unsigned long long hi8, lo8;
            f4split(f, hi8, lo8);
            uint32_t off = (uint32_t)nl * 128 + 2 * kl;
            *(unsigned long long*)(dst + swz(off)) = hi8;
            *(unsigned long long*)(dst + swz(off + 64)) = lo8;
        }
    }
}

// ---------------------------------------------------------------------------
// K1: dec_feat, 4 batches per block (Ws row reuse). grid (8,32) x 128
// ---------------------------------------------------------------------------
__global__ void dec_feat_kernel(const float* __restrict__ h,
                                const float* __restrict__ c,
                                const float* __restrict__ Ws,
                                const float* __restrict__ Wsb) {
    __shared__ float st[4][DIM];
    const int b0 = blockIdx.y * 4;
    const int e = blockIdx.x * 128 + threadIdx.x;
    for (int d = threadIdx.x; d < DIM; d += 128)
#pragma unroll
        for (int bb = 0; bb < 4; bb++) {
            const int b = b0 + bb;
            st[bb][d] = (d < HID) ? h[b * HID + d] : c[b * HID + d - HID];
        }
    __syncthreads();
    const float* wrow = Ws + (size_t)e * DIM;
    const float bias = Wsb[e];
    float a0 = bias, a1 = bias, a2 = bias, a3 = bias;
#pragma unroll 4
    for (int d = 0; d < DIM; d++) {
        const float w = wrow[d];
        a0 = fmaf(st[0][d], w, a0);
        a1 = fmaf(st[1][d], w, a1);
        a2 = fmaf(st[2][d], w, a2);
        a3 = fmaf(st[3][d], w, a3);
    }
    g_dec[(b0 + 0) * DIM + e] = a0;
    g_dec[(b0 + 1) * DIM + e] = a1;
    g_dec[(b0 + 2) * DIM + e] = a2;
    g_dec[(b0 + 3) * DIM + e] = a3;
}

// ---------------------------------------------------------------------------
// K2: fused score. tcgen05 GEMM on 'a'-targets; FFMA2 GEMM otherwise.
// grid 512 x 256 threads for BOTH variants.
// ---------------------------------------------------------------------------
__global__ __launch_bounds__(256)
void score_kernel(const float* __restrict__ enc,
                  const float* __restrict__ Wh,
                  const float* __restrict__ cov,
                  const float* __restrict__ v,
                  const float* __restrict__ wc) {
#if HAS_TC
    extern __shared__ __align__(1024) char smem[];
    const uint32_t sb = s2u(smem);
    const int tid = threadIdx.x, wid = tid >> 5, lane = tid & 31;
    const int row0 = blockIdx.x * 128;
    const int b = row0 >> 9;
    const bool ctrl = (tid == 224);   // MMA/copy control thread (warp 7)

    if (wid == 0) TC_ALLOC(sb + SM_TMEMP, 512);
    if (tid == 0) {
        MBAR_INIT(sb + SM_BF0, 1);   MBAR_INIT(sb + SM_BF1, 1);
        MBAR_INIT(sb + SM_ED0, 1);   MBAR_INIT(sb + SM_ED1, 1);
        MBAR_INIT(sb + SM_AF0, 256); MBAR_INIT(sb + SM_AF1, 256);
    }
    __syncthreads();
    uint32_t tb;
    asm volatile("ld.shared.b32 %0, [%1];" : "=r"(tb) : "r"(sb + SM_TMEMP));

    const int r = tid >> 1, hk = tid & 1;              // A-store mapping
    const float* aptr = enc + (size_t)(row0 + r) * DIM + hk * 16;
    char* Ac[2] = {smem + SM_A0, smem + SM_A1};
    const uint32_t Asm[2] = {sb + SM_A0, sb + SM_A1};
    const uint32_t Bsm[2] = {sb + SM_B0, sb + SM_B1};
    const uint32_t BF[2] = {sb + SM_BF0, sb + SM_BF1};
    const uint32_t ED[2] = {sb + SM_ED0, sb + SM_ED1};
    const uint32_t AF[2] = {sb + SM_AF0, sb + SM_AF1};
    int edph[2] = {0, 0}, bfph[2] = {0, 0}, afph[2] = {0, 0};
    bool pend[2] = {false, false};

    const int sp = wid & 3, hf = wid >> 2;             // epilogue mapping
    const int er = sp * 32 + lane;
    const float covr = cov[b * SEQ + (row0 & 511) + er];
    float scacc = 0.f;

    float* sdec = (float*)(smem + SM_DEC);
    float* swc_ = (float*)(smem + SM_WC);
    float* sv_  = (float*)(smem + SM_V);

    float4 pf[4];
#pragma unroll
    for (int q = 0; q < 4; q++) pf[q] = *(const float4*)(aptr + q * 4);

    int gi = 0;
    for (int pass = 0; pass < 2; ++pass) {
        for (int it = 0; it < NITER; ++it, ++gi) {
            const int p = gi & 1;
            // stage free? (MMAs from gi-2 done)
            if (pend[p]) { WAITP(ED[p], edph[p]); edph[p] ^= 1; pend[p] = false; }
            // prefetch B for THIS iteration as early as possible: the copy
            // overlaps the previous iteration's MMA execution + A conversion.
            if (ctrl) {
                MBAR_EXPECT(BF[p], 65536u);
                bulkcp(Bsm[p], g_whb + ((size_t)it * 2 + pass) * 65536, 65536u, BF[p]);
            }
            // A convert + store (all 256 threads)
#pragma unroll
            for (int q = 0; q < 4; q++) {
                unsigned long long hi8, lo8;
                f4split(pf[q], hi8, lo8);
                const uint32_t off = (uint32_t)r * 128 + hk * 32 + q * 8;
                *(unsigned long long*)(Ac[p] + swz(off)) = hi8;
                *(unsigned long long*)(Ac[p] + swz(off + 64)) = lo8;
            }
            if (gi < 63) {
                const int nit = (it + 1 == NITER) ? 0 : it + 1;
#pragma unroll
                for (int q = 0; q < 4; q++)
                    pf[q] = *(const float4*)(aptr + nit * 32 + q * 4);
            }
            asm volatile("fence.proxy.async.shared::cta;" ::: "memory");
            MBAR_ARRIVE(AF[p]);
            // control thread: wait A complete + B arrived, issue MMAs
            if (ctrl) {
                WAITP(AF[p], afph[p]); afph[p] ^= 1;
                WAITP(BF[p], bfph[p]); bfph[p] ^= 1;
                const unsigned long long adb = mkdesc(Asm[p]);
#pragma unroll
                for (int c = 0; c < NCH; c++) {
                    const unsigned long long bdb = mkdesc(Bsm[p] + c * 16384);
                    const unsigned dtm = tb + c * 128;
#pragma unroll
                    for (int ks = 0; ks < 2; ks++) {
                        const unsigned long long ah = adb + ks * 2, al = ah + 4;
                        const unsigned long long bh = bdb + ks * 2, bl = bh + 4;
                        mma_bf16_ss(dtm, ah, bh, IDESC, !(it == 0 && ks == 0));
                        mma_bf16_ss(dtm, ah, bl, IDESC, true);
                        mma_bf16_ss(dtm, al, bh, IDESC, true);
                    }
                }
                TC_COMMIT(ED[p]);
            }
            pend[p] = true;
        }
        // stage epilogue vectors for this pass
        for (int i = tid; i < 512; i += 256) {
            const int e = pass * 512 + i;
            sdec[i] = g_dec[b * DIM + e];
            swc_[i] = wc[e];
            sv_[i] = v[e];
        }
        // drain both stages
#pragma unroll
        for (int p = 0; p < 2; p++)
            if (pend[p]) { WAITP(ED[p], edph[p]); edph[p] ^= 1; pend[p] = false; }
        TC_FENCE_AFTER();
        __syncthreads();
        // epilogue: read D, add dec + cov*wc, tanh, dot v
        for (int c = 0; c < NCH; c++) {
            uint32_t dreg[64];
            TC_LD_X32(dreg, tb + c * 128 + hf * 64);
            TC_LD_X32(dreg + 32, tb + c * 128 + hf * 64 + 32);
            TC_WAIT_LD();
            const int ebl = c * 128 + hf * 64;
#pragma unroll
            for (int j = 0; j < 64; j++) {
                const float x = __uint_as_float(dreg[j]) + sdec[ebl + j] +
                                covr * swc_[ebl + j];
                scacc += sv_[ebl + j] * tanh_hw(x);
            }
        }
        TC_FENCE_BEFORE();
        __syncthreads();
    }

    float* ssm = (float*)(smem + SM_SSM);
    if (hf == 0) ssm[er] = scacc;
    __syncthreads();
    if (hf == 1) g_score[row0 + er] = ssm[er] + scacc;
    __syncthreads();
    if (tid == 0) {
        MBAR_INVAL(sb + SM_BF0); MBAR_INVAL(sb + SM_BF1);
        MBAR_INVAL(sb + SM_ED0); MBAR_INVAL(sb + SM_ED1);
        MBAR_INVAL(sb + SM_AF0); MBAR_INVAL(sb + SM_AF1);
    }
    __syncthreads();
    if (wid == 0) { TC_RELINQ(); TC_DEALLOC(tb, 512); }

#else  // ------------------- FFMA2 fallback (proven R2 path) ----------------
    __shared__ __align__(16) float As[16][128];
    __shared__ __align__(16) float Bs[16][128];

    const int tid = threadIdx.x;
    const int tx = tid & 15;
    const int ty = tid >> 4;
    const int row0 = blockIdx.x * 128;
    const int b = row0 >> 9;
    const int sbase = (row0 & 511) + ty * 8;
    const int lr = tid >> 2;
    const int lc = (tid & 3) << 2;

    float rowpart[8];
#pragma unroll
    for (int i = 0; i < 8; i++) rowpart[i] = 0.f;

    for (int et = 0; et < 8; ++et) {
        const int n0 = et * 128;
        unsigned long long accp[8][4];
#pragma unroll
        for (int i = 0; i < 8; i++)
#pragma unroll
            for (int j = 0; j < 4; j++) accp[i][j] = 0ull;

        for (int k0 = 0; k0 < DIM; k0 += 16) {
            float4 a0 = *(const float4*)&enc[(size_t)(row0 + lr) * DIM + k0 + lc];
            float4 a1 = *(const float4*)&enc[(size_t)(row0 + lr + 64) * DIM + k0 + lc];
            float4 b0 = *(const float4*)&Wh[(size_t)(n0 + lr) * DIM + k0 + lc];
            float4 b1 = *(const float4*)&Wh[(size_t)(n0 + lr + 64) * DIM + k0 + lc];
            __syncthreads();
            As[lc + 0][lr] = a0.x; As[lc + 1][lr] = a0.y;
            As[lc + 2][lr] = a0.z; As[lc + 3][lr] = a0.w;
            As[lc + 0][lr + 64] = a1.x; As[lc + 1][lr + 64] = a1.y;
            As[lc + 2][lr + 64] = a1.z; As[lc + 3][lr + 64] = a1.w;
            Bs[lc + 0][lr] = b0.x; Bs[lc + 1][lr] = b0.y;
            Bs[lc + 2][lr] = b0.z; Bs[lc + 3][lr] = b0.w;
            Bs[lc + 0][lr + 64] = b1.x; Bs[lc + 1][lr + 64] = b1.y;
            Bs[lc + 2][lr + 64] = b1.z; Bs[lc + 3][lr + 64] = b1.w;
            __syncthreads();
#pragma unroll
            for (int k = 0; k < 16; k++) {
                const float4 m0 = *(const float4*)&As[k][ty * 8];
                const float4 m1 = *(const float4*)&As[k][ty * 8 + 4];
                const ulonglong2 nb0 = *(const ulonglong2*)&Bs[k][tx * 8];
                const ulonglong2 nb1 = *(const ulonglong2*)&Bs[k][tx * 8 + 4];
                unsigned long long np[4] = {nb0.x, nb0.y, nb1.x, nb1.y};
                float mv[8] = {m0.x, m0.y, m0.z, m0.w, m1.x, m1.y, m1.z, m1.w};
#pragma unroll
                for (int i = 0; i < 8; i++) {
                    const unsigned long long mm = dup2(mv[i]);
#pragma unroll
                    for (int j = 0; j < 4; j++)
                        fma2(accp[i][j], mm, np[j]);
                }
            }
        }
        const int ebase = n0 + tx * 8;
        float dv[8], wcv[8], vv[8];
#pragma unroll
        for (int j = 0; j < 8; j++) {
            dv[j]  = g_dec[b * DIM + ebase + j];
            wcv[j] = wc[ebase + j];
            vv[j]  = v[ebase + j];
        }
#pragma unroll
        for (int i = 0; i < 8; i++) {
            const float cv = cov[b * SEQ + sbase + i];
            float p = 0.f;
#pragma unroll
            for (int j = 0; j < 4; j++) {
                const float x0 = lo32(accp[i][j]) + dv[2 * j]     + cv * wcv[2 * j];
                const float x1 = hi32(accp[i][j]) + dv[2 * j + 1] + cv * wcv[2 * j + 1];
                p += vv[2 * j] * tanhf(x0) + vv[2 * j + 1] * tanhf(x1);
            }
            rowpart[i] += p;
        }
    }
#pragma unroll
    for (int off = 8; off >= 1; off >>= 1)
#pragma unroll
        for (int i = 0; i < 8; i++)
            rowpart[i] += __shfl_xor_sync(0xffffffffu, rowpart[i], off);
    if (tx == 0) {
#pragma unroll
        for (int i = 0; i < 8; i++)
            g_score[row0 + ty * 8 + i] = rowpart[i];
    }
#endif
}

// ---------------------------------------------------------------------------
// K3: masked softmax + renorm; writes aw and new_coverage
// ---------------------------------------------------------------------------
__global__ void softmax_kernel(const float* __restrict__ mask,
                               const float* __restrict__ cov,
                               float* __restrict__ out) {
    __shared__ float red[SEQ];
    const int b = blockIdx.x, s = threadIdx.x;
    const float sc = g_score[b * SEQ + s];
    red[s] = sc;
    __syncthreads();
    for (int off = 256; off > 0; off >>= 1) {
        if (s < off) red[s] = fmaxf(red[s], red[s + off]);
        __syncthreads();
    }
    const float mx = red[0];
    __syncthreads();
    const float ex = expf(sc - mx);
    red[s] = ex;
    __syncthreads();
    for (int off = 256; off > 0; off >>= 1) {
        if (s < off) red[s] += red[s + off];
        __syncthreads();
    }
    const float sum = red[0];
    __syncthreads();
    const float aw0 = (ex / sum) * mask[b * SEQ + s];
    red[s] = aw0;
    __syncthreads();
    for (int off = 256; off > 0; off >>= 1) {
        if (s < off) red[s] += red[s + off];
        __syncthreads();
    }
    const float aw = aw0 / red[0];
    out[BATCH * DIM + b * SEQ + s] = aw;
    out[BATCH * DIM + BATCH * SEQ + b * SEQ + s] = cov[b * SEQ + s] + aw;
}

// ---------------------------------------------------------------------------
// K4: context split over 8 s-slices + deterministic combine
// grid (8, BATCH) x 512 threads; thread owns 2 d's (float2), slice = 64 s
// ---------------------------------------------------------------------------
__global__ void context_part_kernel(const float* __restrict__ enc,
                                    const float* __restrict__ aw) {
    __shared__ float aws[64];
    const int q = blockIdx.x, b = blockIdx.y;
    if (threadIdx.x < 64) aws[threadIdx.x] = aw[b * SEQ + q * 64 + threadIdx.x];
    __syncthreads();
    const int d = threadIdx.x * 2;
    const float* ebase = enc + (size_t)b * SEQ * DIM + (size_t)(q * 64) * DIM + d;
    float2 acc = make_float2(0.f, 0.f);
#pragma unroll 8
    for (int s = 0; s < 64; s++) {
        const float2 e2 = *(const float2*)&ebase[(size_t)s * DIM];
        const float w = aws[s];
        acc.x = fmaf(w, e2.x, acc.x);
        acc.y = fmaf(w, e2.y, acc.y);
    }
    *(float2*)&g_cpart[(q * BATCH + b) * DIM + d] = acc;
}
__global__ void context_sum_kernel(float* __restrict__ outc) {
    const int i = blockIdx.x * 256 + threadIdx.x;
    const int N = BATCH * DIM;
    float s0 = g_cpart[i]         + g_cpart[N + i];
    float s1 = g_cpart[2 * N + i] + g_cpart[3 * N + i];
    float s2 = g_cpart[4 * N + i] + g_cpart[5 * N + i];
    float s3 = g_cpart[6 * N + i] + g_cpart[7 * N + i];
    outc[i] = (s0 + s1) + (s2 + s3);
}

// ---------------------------------------------------------------------------
extern "C" void kernel_launch(void* const* d_in, const int* in_sizes, int n_in,
                              void* d_out, int out_size) {
    const float* h_dec = (const float*)d_in[0];
    const float* c_dec = (const float*)d_in[1];
    const float* enc   = (const float*)d_in[2];
    const float* mask  = (const float*)d_in[3];
    const float* cov   = (const float*)d_in[4];
    const float* Wh    = (const float*)d_in[5];
    const float* Ws    = (const float*)d_in[6];
    const float* Wsb   = (const float*)d_in[7];
    const float* v     = (const float*)d_in[8];
    const float* wc    = (const float*)d_in[9];
    float* out = (float*)d_out;

    // Which variant did the runtime load? tc path has no static smem;
    // fallback carries 16KB static As/Bs.
    cudaFuncAttributes fa;
    cudaFuncGetAttributes(&fa, score_kernel);
    const bool tc = (fa.sharedSizeBytes < 8192);
    size_t dyn = 0;
    if (tc) {
        cudaFuncSetAttribute(score_kernel,
                             cudaFuncAttributeMaxDynamicSharedMemorySize, SMEM_DYN);
        dyn = SMEM_DYN;
        convB_kernel<<<dim3(32, 2), 256>>>(Wh);
    }
    dec_feat_kernel<<<dim3(8, 32), 128>>>(h_dec, c_dec, Ws, Wsb);
    score_kernel<<<MROWS / 128, 256, dyn>>>(enc, Wh, cov, v, wc);
    softmax_kernel<<<BATCH, SEQ>>>(mask, cov, out);
    context_part_kernel<<<dim3(8, BATCH), 512>>>(enc, out + BATCH * DIM);
    context_sum_kernel<<<BATCH * DIM / 256, 256>>>(out);
}

// round 10
// speedup vs baseline: 6.6147x; 1.2406x over previous
#include <cuda_runtime.h>
#include <cuda_bf16.h>
#include <cstdint>

#define BATCH 128
#define SEQ   512
#define HID   512
#define DIM   1024
#define MROWS (BATCH*SEQ)
#define NITER 32
#define NCH   4

// Arch-specific (sm_103a/sm_100a) feature gate: tcgen05 / cp.async.bulk are
// only legal in 'a'-target compilation passes. Other passes get the FFMA2
// fallback under the SAME kernel symbol.
#if defined(__CUDA_ARCH_FEAT_SM103_ALL) || defined(__CUDA_ARCH_FEAT_SM100_ALL) || defined(__CUDA_ARCH_FEAT_SM101_ALL)
#define HAS_TC 1
#else
#define HAS_TC 0
#endif

__device__ float g_dec[BATCH * DIM];
__device__ float g_score[BATCH * SEQ];
__device__ float g_cpart[8 * BATCH * DIM];
// Wh pre-converted: [kb=32][half=2] 64KB blocks; block = 512 n-rows x 128B
// (row = [32 hi bf16 | 32 lo bf16]), SW128-swizzled.
__device__ __align__(1024) unsigned char g_whb[32 * 2 * 65536];

// ---------------------------------------------------------------------------
// generic helpers (legal on all targets)
// ---------------------------------------------------------------------------
__device__ __forceinline__ uint32_t swz(uint32_t o) { return o ^ ((o >> 3) & 0x70); }

__device__ __forceinline__ unsigned packbf2(float up, float lo) {
    unsigned r;  // [31:16] = bf16(up), [15:0] = bf16(lo)
    asm("cvt.rn.bf16x2.f32 %0, %1, %2;" : "=r"(r) : "f"(up), "f"(lo));
    return r;
}
// split float4 into packed hi / lo bf16 quads (8B each); residual exact in fp32
__device__ __forceinline__ void f4split(float4 f, unsigned long long& hi8,
                                        unsigned long long& lo8) {
    unsigned h01 = packbf2(f.y, f.x);
    unsigned h23 = packbf2(f.w, f.z);
    float h0 = __uint_as_float(h01 << 16);
    float h1 = __uint_as_float(h01 & 0xFFFF0000u);
    float h2 = __uint_as_float(h23 << 16);
    float h3 = __uint_as_float(h23 & 0xFFFF0000u);
    unsigned l01 = packbf2(f.y - h1, f.x - h0);
    unsigned l23 = packbf2(f.w - h3, f.z - h2);
    hi8 = (unsigned long long)h01 | ((unsigned long long)h23 << 32);
    lo8 = (unsigned long long)l01 | ((unsigned long long)l23 << 32);
}
__device__ __forceinline__ float tanh_hw(float x) {
    float r;
    asm("tanh.approx.f32 %0, %1;" : "=f"(r) : "f"(x));
    return r;
}
// packed f32x2 (fallback GEMM)
__device__ __forceinline__ void fma2(unsigned long long& c,
                                     unsigned long long a,
                                     unsigned long long b) {
    asm("fma.rn.f32x2 %0, %1, %2, %3;" : "=l"(c) : "l"(a), "l"(b), "l"(c));
}
__device__ __forceinline__ unsigned long long dup2(float x) {
    unsigned long long r;
    unsigned int u = __float_as_uint(x);
    asm("mov.b64 %0, {%1, %1};" : "=l"(r) : "r"(u));
    return r;
}
__device__ __forceinline__ float lo32(unsigned long long v) {
    return __uint_as_float((unsigned int)v);
}
__device__ __forceinline__ float hi32(unsigned long long v) {
    return __uint_as_float((unsigned int)(v >> 32));
}

#if HAS_TC
// ---------------------------------------------------------------------------
// tcgen05 / mbarrier primitives (only in 'a'-target passes)
// ---------------------------------------------------------------------------
__device__ __forceinline__ uint32_t s2u(const void* p) {
    uint32_t a;
    asm("{ .reg .u64 t; cvta.to.shared.u64 t, %1; cvt.u32.u64 %0, t; }"
        : "=r"(a) : "l"(p));
    return a;
}
__device__ __forceinline__ unsigned long long mkdesc(uint32_t addr) {
    // SW128, version=1 (Blackwell), SBO=64, LBO=1
    return 0x4000404000010000ull | ((unsigned long long)(addr >> 4) & 0x3FFF);
}
#define MBAR_INIT(a, c) \
    asm volatile("mbarrier.init.shared.b64 [%0], %1;" :: "r"(a), "r"(c) : "memory")
#define MBAR_INVAL(a) \
    asm volatile("mbarrier.inval.shared.b64 [%0];" :: "r"(a) : "memory")
#define MBAR_EXPECT(a, b) \
    asm volatile("mbarrier.arrive.expect_tx.shared.b64 _, [%0], %1;" :: "r"(a), "r"(b) : "memory")
#define WAITP(mbar, ph) do {                                                        \
    asm volatile("{\n\t.reg .pred P;\n\t"                                           \
        "WL_%=:\n\t"                                                                \
        "mbarrier.try_wait.parity.acquire.cta.shared::cta.b64 P, [%0], %1, 0x989680;\n\t" \
        "@P bra.uni WD_%=;\n\t"                                                     \
        "bra.uni WL_%=;\n\t"                                                        \
        "WD_%=:\n\t}"                                                               \
        :: "r"(mbar), "r"((unsigned)(ph)) : "memory");                              \
} while (0)
#define TC_ALLOC(sa, n) \
    asm volatile("tcgen05.alloc.cta_group::1.sync.aligned.shared::cta.b32 [%0], %1;" \
                 :: "r"(sa), "r"((unsigned)(n)) : "memory")
#define TC_RELINQ() \
    asm volatile("tcgen05.relinquish_alloc_permit.cta_group::1.sync.aligned;")
#define TC_DEALLOC(t, n) \
    asm volatile("tcgen05.dealloc.cta_group::1.sync.aligned.b32 %0, %1;" :: "r"(t), "r"((unsigned)(n)))
#define TC_COMMIT(mbar) \
    asm volatile("tcgen05.commit.cta_group::1.mbarrier::arrive::one.shared::cluster.b64 [%0];" \
                 :: "r"(mbar) : "memory")
#define TC_WAIT_LD()      asm volatile("tcgen05.wait::ld.sync.aligned;" ::: "memory")
#define TC_FENCE_BEFORE() asm volatile("tcgen05.fence::before_thread_sync;" ::: "memory")
#define TC_FENCE_AFTER()  asm volatile("tcgen05.fence::after_thread_sync;" ::: "memory")
#define TC_LD_X32(r, ta)                                                    \
    asm volatile("tcgen05.ld.sync.aligned.32x32b.x32.b32 "                  \
        "{%0, %1, %2, %3, %4, %5, %6, %7, "                                 \
        " %8, %9, %10, %11, %12, %13, %14, %15, "                           \
        " %16, %17, %18, %19, %20, %21, %22, %23, "                         \
        " %24, %25, %26, %27, %28, %29, %30, %31}, [%32];"                  \
        : "=r"((r)[0]),  "=r"((r)[1]),  "=r"((r)[2]),  "=r"((r)[3]),        \
          "=r"((r)[4]),  "=r"((r)[5]),  "=r"((r)[6]),  "=r"((r)[7]),        \
          "=r"((r)[8]),  "=r"((r)[9]),  "=r"((r)[10]), "=r"((r)[11]),       \
          "=r"((r)[12]), "=r"((r)[13]), "=r"((r)[14]), "=r"((r)[15]),       \
          "=r"((r)[16]), "=r"((r)[17]), "=r"((r)[18]), "=r"((r)[19]),       \
          "=r"((r)[20]), "=r"((r)[21]), "=r"((r)[22]), "=r"((r)[23]),       \
          "=r"((r)[24]), "=r"((r)[25]), "=r"((r)[26]), "=r"((r)[27]),       \
          "=r"((r)[28]), "=r"((r)[29]), "=r"((r)[30]), "=r"((r)[31])        \
        : "r"(ta))

__device__ __forceinline__ void mma_bf16_ss(unsigned d, unsigned long long ad,
                                            unsigned long long bd,
                                            unsigned idesc, bool acc) {
    unsigned e = acc ? 1u : 0u;
    asm volatile("{\n\t.reg .pred p;\n\tsetp.ne.u32 p, %5, 0;\n\t"
        "tcgen05.mma.cta_group::1.kind::f16 [%0], %1, %2, %3, {%4, %4, %4, %4}, p;\n\t}"
        :: "r"(d), "l"(ad), "l"(bd), "r"(idesc), "r"(0u), "r"(e) : "memory");
}
__device__ __forceinline__ void bulkcp(unsigned dst, const void* src,
                                       unsigned bytes, unsigned mbar) {
    asm volatile(
        "cp.async.bulk.shared::cta.global.mbarrier::complete_tx::bytes [%0], [%1], %2, [%3];"
        :: "r"(dst), "l"(src), "r"(bytes), "r"(mbar) : "memory");
}
// idesc kind::f16: dtype F32(1<<4), atype BF16(1<<7), btype BF16(1<<10),
// N=128 (16<<17), M=128 (8<<24)
#define IDESC 0x8200490u
#endif  // HAS_TC

// dynamic smem layout (tc path)
#define SM_TMEMP 0
#define SM_BF0   8
#define SM_BF1   16
#define SM_ED0   24
#define SM_ED1   32
#define SM_SSM   64
#define SM_A0    1024
#define SM_A1    17408
#define SM_B0    33792
#define SM_B1    99328
#define SM_DEC   164864
#define SM_WC    166912
#define SM_V     168960
#define SMEM_DYN 171008

// ---------------------------------------------------------------------------
// convB: Wh fp32 -> pre-tiled, pre-swizzled hi/lo bf16 blocks. grid (32,2)x256
// ---------------------------------------------------------------------------
__global__ void convB_kernel(const float* __restrict__ Wh) {
    const int kb = blockIdx.x, half = blockIdx.y;
    unsigned char* dst = g_whb + (size_t)(kb * 2 + half) * 65536;
    const int rb = threadIdx.x >> 1, hk = threadIdx.x & 1;
    for (int i = 0; i < 4; i++) {
        const int nl = rb + i * 128;
        const int n = half * 512 + nl;
#pragma unroll
        for (int q = 0; q < 4; q++) {
            const int kl = hk * 16 + q * 4;
            float4 f = *(const float4*)&Wh[(size_t)n * DIM + kb * 32 + kl];
            unsigned long long hi8, lo8;
            f4split(f, hi8, lo8);
            uint32_t off = (uint32_t)nl * 128 + 2 * kl;
            *(unsigned long long*)(dst + swz(off)) = hi8;
            *(unsigned long long*)(dst + swz(off + 64)) = lo8;
        }
    }
}

// ---------------------------------------------------------------------------
// K1: dec_feat, 4 batches per block (Ws row reuse). grid (8,32) x 128
// ---------------------------------------------------------------------------
__global__ void dec_feat_kernel(const float* __restrict__ h,
                                const float* __restrict__ c,
                                const float* __restrict__ Ws,
                                const float* __restrict__ Wsb) {
    __shared__ float st[4][DIM];
    const int b0 = blockIdx.y * 4;
    const int e = blockIdx.x * 128 + threadIdx.x;
    for (int d = threadIdx.x; d < DIM; d += 128)
#pragma unroll
        for (int bb = 0; bb < 4; bb++) {
            const int b = b0 + bb;
            st[bb][d] = (d < HID) ? h[b * HID + d] : c[b * HID + d - HID];
        }
    __syncthreads();
    const float* wrow = Ws + (size_t)e * DIM;
    const float bias = Wsb[e];
    float a0 = bias, a1 = bias, a2 = bias, a3 = bias;
#pragma unroll 4
    for (int d = 0; d < DIM; d++) {
        const float w = wrow[d];
        a0 = fmaf(st[0][d], w, a0);
        a1 = fmaf(st[1][d], w, a1);
        a2 = fmaf(st[2][d], w, a2);
        a3 = fmaf(st[3][d], w, a3);
    }
    g_dec[(b0 + 0) * DIM + e] = a0;
    g_dec[(b0 + 1) * DIM + e] = a1;
    g_dec[(b0 + 2) * DIM + e] = a2;
    g_dec[(b0 + 3) * DIM + e] = a3;
}

// ---------------------------------------------------------------------------
// K2: fused score. tcgen05 GEMM on 'a'-targets; FFMA2 GEMM otherwise.
// grid 512 x 256 threads for BOTH variants.
// tc path: two alternating MMA control threads (tid 254 -> stage 0,
// tid 255 -> stage 1) so the MMA queue-full stall is off the critical path;
// bar.sync (not a 256-arrival mbarrier) publishes the A tile.
// ---------------------------------------------------------------------------
__global__ __launch_bounds__(256)
void score_kernel(const float* __restrict__ enc,
                  const float* __restrict__ Wh,
                  const float* __restrict__ cov,
                  const float* __restrict__ v,
                  const float* __restrict__ wc) {
#if HAS_TC
    extern __shared__ __align__(1024) char smem[];
    const uint32_t sb = s2u(smem);
    const int tid = threadIdx.x, wid = tid >> 5, lane = tid & 31;
    const int row0 = blockIdx.x * 128;
    const int b = row0 >> 9;

    if (wid == 0) TC_ALLOC(sb + SM_TMEMP, 512);
    if (tid == 0) {
        MBAR_INIT(sb + SM_BF0, 1); MBAR_INIT(sb + SM_BF1, 1);
        MBAR_INIT(sb + SM_ED0, 1); MBAR_INIT(sb + SM_ED1, 1);
    }
    __syncthreads();
    uint32_t tb;
    asm volatile("ld.shared.b32 %0, [%1];" : "=r"(tb) : "r"(sb + SM_TMEMP));

    const int r = tid >> 1, hk = tid & 1;              // A-store mapping
    const float* aptr = enc + (size_t)(row0 + r) * DIM + hk * 16;
    char* Ac[2] = {smem + SM_A0, smem + SM_A1};
    const uint32_t Asm[2] = {sb + SM_A0, sb + SM_A1};
    const uint32_t Bsm[2] = {sb + SM_B0, sb + SM_B1};
    const uint32_t BF[2] = {sb + SM_BF0, sb + SM_BF1};
    const uint32_t ED[2] = {sb + SM_ED0, sb + SM_ED1};
    int edph[2] = {0, 0};
    int mybfph = 0;                                    // per-ctrl BF phase
    bool pend[2] = {false, false};
    // ctrl roles: tid 254 owns stage 0, tid 255 owns stage 1
    const int myctrl_stage = (tid == 254) ? 0 : (tid == 255) ? 1 : -1;

    const int sp = wid & 3, hf = wid >> 2;             // epilogue mapping
    const int er = sp * 32 + lane;
    const float covr = cov[b * SEQ + (row0 & 511) + er];
    float scacc = 0.f;

    float* sdec = (float*)(smem + SM_DEC);
    float* swc_ = (float*)(smem + SM_WC);
    float* sv_  = (float*)(smem + SM_V);

    float4 pf[4];
#pragma unroll
    for (int q = 0; q < 4; q++) pf[q] = *(const float4*)(aptr + q * 4);

    int gi = 0;
    for (int pass = 0; pass < 2; ++pass) {
        for (int it = 0; it < NITER; ++it, ++gi) {
            const int p = gi & 1;
            // stage free? (MMAs from gi-2 done) — all threads wait
            if (pend[p]) { WAITP(ED[p], edph[p]); edph[p] ^= 1; pend[p] = false; }
            // issue B prefetch for THIS iteration (overlaps prior MMA + conv)
            if (tid == 0) {
                MBAR_EXPECT(BF[p], 65536u);
                bulkcp(Bsm[p], g_whb + ((size_t)it * 2 + pass) * 65536, 65536u, BF[p]);
            }
            // A convert + store (all 256 threads)
#pragma unroll
            for (int q = 0; q < 4; q++) {
                unsigned long long hi8, lo8;
                f4split(pf[q], hi8, lo8);
                const uint32_t off = (uint32_t)r * 128 + hk * 32 + q * 8;
                *(unsigned long long*)(Ac[p] + swz(off)) = hi8;
                *(unsigned long long*)(Ac[p] + swz(off + 64)) = lo8;
            }
            if (gi < 63) {
                const int nit = (it + 1 == NITER) ? 0 : it + 1;
#pragma unroll
                for (int q = 0; q < 4; q++)
                    pf[q] = *(const float4*)(aptr + nit * 32 + q * 4);
            }
            asm volatile("fence.proxy.async.shared::cta;" ::: "memory");
            __syncthreads();   // A tile published (HW barrier, no mbarrier cost)
            // stage-owning control thread: wait B, issue MMAs, commit
            if (myctrl_stage == p) {
                WAITP(BF[p], mybfph); mybfph ^= 1;
                const unsigned long long adb = mkdesc(Asm[p]);
#pragma unroll
                for (int c = 0; c < NCH; c++) {
                    const unsigned long long bdb = mkdesc(Bsm[p] + c * 16384);
                    const unsigned dtm = tb + c * 128;
#pragma unroll
                    for (int ks = 0; ks < 2; ks++) {
                        const unsigned long long ah = adb + ks * 2, al = ah + 4;
                        const unsigned long long bh = bdb + ks * 2, bl = bh + 4;
                        mma_bf16_ss(dtm, ah, bh, IDESC, !(it == 0 && ks == 0));
                        mma_bf16_ss(dtm, ah, bl, IDESC, true);
                        mma_bf16_ss(dtm, al, bh, IDESC, true);
                    }
                }
                TC_COMMIT(ED[p]);
            }
            pend[p] = true;
        }
        // stage epilogue vectors for this pass
        for (int i = tid; i < 512; i += 256) {
            const int e = pass * 512 + i;
            sdec[i] = g_dec[b * DIM + e];
            swc_[i] = wc[e];
            sv_[i] = v[e];
        }
        // drain both stages
#pragma unroll
        for (int p = 0; p < 2; p++)
            if (pend[p]) { WAITP(ED[p], edph[p]); edph[p] ^= 1; pend[p] = false; }
        TC_FENCE_AFTER();
        __syncthreads();
        // epilogue: read D, add dec + cov*wc, tanh, dot v
        for (int c = 0; c < NCH; c++) {
            uint32_t dreg[64];
            TC_LD_X32(dreg, tb + c * 128 + hf * 64);
            TC_LD_X32(dreg + 32, tb + c * 128 + hf * 64 + 32);
            TC_WAIT_LD();
            const int ebl = c * 128 + hf * 64;
#pragma unroll
            for (int j = 0; j < 64; j++) {
                const float x = __uint_as_float(dreg[j]) + sdec[ebl + j] +
                                covr * swc_[ebl + j];
                scacc += sv_[ebl + j] * tanh_hw(x);
            }
        }
        TC_FENCE_BEFORE();
        __syncthreads();
    }

    float* ssm = (float*)(smem + SM_SSM);
    if (hf == 0) ssm[er] = scacc;
    __syncthreads();
    if (hf == 1) g_score[row0 + er] = ssm[er] + scacc;
    __syncthreads();
    if (tid == 0) {
        MBAR_INVAL(sb + SM_BF0); MBAR_INVAL(sb + SM_BF1);
        MBAR_INVAL(sb + SM_ED0); MBAR_INVAL(sb + SM_ED1);
    }
    __syncthreads();
    if (wid == 0) { TC_RELINQ(); TC_DEALLOC(tb, 512); }

#else  // ------------------- FFMA2 fallback (proven R2 path) ----------------
    __shared__ __align__(16) float As[16][128];
    __shared__ __align__(16) float Bs[16][128];

    const int tid = threadIdx.x;
    const int tx = tid & 15;
    const int ty = tid >> 4;
    const int row0 = blockIdx.x * 128;
    const int b = row0 >> 9;
    const int sbase = (row0 & 511) + ty * 8;
    const int lr = tid >> 2;
    const int lc = (tid & 3) << 2;

    float rowpart[8];
#pragma unroll
    for (int i = 0; i < 8; i++) rowpart[i] = 0.f;

    for (int et = 0; et < 8; ++et) {
        const int n0 = et * 128;
        unsigned long long accp[8][4];
#pragma unroll
        for (int i = 0; i < 8; i++)
#pragma unroll
            for (int j = 0; j < 4; j++) accp[i][j] = 0ull;

        for (int k0 = 0; k0 < DIM; k0 += 16) {
            float4 a0 = *(const float4*)&enc[(size_t)(row0 + lr) * DIM + k0 + lc];
            float4 a1 = *(const float4*)&enc[(size_t)(row0 + lr + 64) * DIM + k0 + lc];
            float4 b0 = *(const float4*)&Wh[(size_t)(n0 + lr) * DIM + k0 + lc];
            float4 b1 = *(const float4*)&Wh[(size_t)(n0 + lr + 64) * DIM + k0 + lc];
            __syncthreads();
            As[lc + 0][lr] = a0.x; As[lc + 1][lr] = a0.y;
            As[lc + 2][lr] = a0.z; As[lc + 3][lr] = a0.w;
            As[lc + 0][lr + 64] = a1.x; As[lc + 1][lr + 64] = a1.y;
            As[lc + 2][lr + 64] = a1.z; As[lc + 3][lr + 64] = a1.w;
            Bs[lc + 0][lr] = b0.x; Bs[lc + 1][lr] = b0.y;
            Bs[lc + 2][lr] = b0.z; Bs[lc + 3][lr] = b0.w;
            Bs[lc + 0][lr + 64] = b1.x; Bs[lc + 1][lr + 64] = b1.y;
            Bs[lc + 2][lr + 64] = b1.z; Bs[lc + 3][lr + 64] = b1.w;
            __syncthreads();
#pragma unroll
            for (int k = 0; k < 16; k++) {
                const float4 m0 = *(const float4*)&As[k][ty * 8];
                const float4 m1 = *(const float4*)&As[k][ty * 8 + 4];
                const ulonglong2 nb0 = *(const ulonglong2*)&Bs[k][tx * 8];
                const ulonglong2 nb1 = *(const ulonglong2*)&Bs[k][tx * 8 + 4];
                unsigned long long np[4] = {nb0.x, nb0.y, nb1.x, nb1.y};
                float mv[8] = {m0.x, m0.y, m0.z, m0.w, m1.x, m1.y, m1.z, m1.w};
#pragma unroll
                for (int i = 0; i < 8; i++) {
                    const unsigned long long mm = dup2(mv[i]);
#pragma unroll
                    for (int j = 0; j < 4; j++)
                        fma2(accp[i][j], mm, np[j]);
                }
            }
        }
        const int ebase = n0 + tx * 8;
        float dv[8], wcv[8], vv[8];
#pragma unroll
        for (int j = 0; j < 8; j++) {
            dv[j]  = g_dec[b * DIM + ebase + j];
            wcv[j] = wc[ebase + j];
            vv[j]  = v[ebase + j];
        }
#pragma unroll
        for (int i = 0; i < 8; i++) {
            const float cv = cov[b * SEQ + sbase + i];
            float p = 0.f;
#pragma unroll
            for (int j = 0; j < 4; j++) {
                const float x0 = lo32(accp[i][j]) + dv[2 * j]     + cv * wcv[2 * j];
                const float x1 = hi32(accp[i][j]) + dv[2 * j + 1] + cv * wcv[2 * j + 1];
                p += vv[2 * j] * tanhf(x0) + vv[2 * j + 1] * tanhf(x1);
            }
            rowpart[i] += p;
        }
    }
#pragma unroll
    for (int off = 8; off >= 1; off >>= 1)
#pragma unroll
        for (int i = 0; i < 8; i++)
            rowpart[i] += __shfl_xor_sync(0xffffffffu, rowpart[i], off);
    if (tx == 0) {
#pragma unroll
        for (int i = 0; i < 8; i++)
            g_score[row0 + ty * 8 + i] = rowpart[i];
    }
#endif
}

// ---------------------------------------------------------------------------
// K3: masked softmax + renorm; writes aw and new_coverage
// ---------------------------------------------------------------------------
__global__ void softmax_kernel(const float* __restrict__ mask,
                               const float* __restrict__ cov,
                               float* __restrict__ out) {
    __shared__ float red[SEQ];
    const int b = blockIdx.x, s = threadIdx.x;
    const float sc = g_score[b * SEQ + s];
    red[s] = sc;
    __syncthreads();
    for (int off = 256; off > 0; off >>= 1) {
        if (s < off) red[s] = fmaxf(red[s], red[s + off]);
        __syncthreads();
    }
    const float mx = red[0];
    __syncthreads();
    const float ex = expf(sc - mx);
    red[s] = ex;
    __syncthreads();
    for (int off = 256; off > 0; off >>= 1) {
        if (s < off) red[s] += red[s + off];
        __syncthreads();
    }
    const float sum = red[0];
    __syncthreads();
    const float aw0 = (ex / sum) * mask[b * SEQ + s];
    red[s] = aw0;
    __syncthreads();
    for (int off = 256; off > 0; off >>= 1) {
        if (s < off) red[s] += red[s + off];
        __syncthreads();
    }
    const float aw = aw0 / red[0];
    out[BATCH * DIM + b * SEQ + s] = aw;
    out[BATCH * DIM + BATCH * SEQ + b * SEQ + s] = cov[b * SEQ + s] + aw;
}

// ---------------------------------------------------------------------------
// K4: context split over 8 s-slices + deterministic combine
// ---------------------------------------------------------------------------
__global__ void context_part_kernel(const float* __restrict__ enc,
                                    const float* __restrict__ aw) {
    __shared__ float aws[64];
    const int q = blockIdx.x, b = blockIdx.y;
    if (threadIdx.x < 64) aws[threadIdx.x] = aw[b * SEQ + q * 64 + threadIdx.x];
    __syncthreads();
    const int d = threadIdx.x * 2;
    const float* ebase = enc + (size_t)b * SEQ * DIM + (size_t)(q * 64) * DIM + d;
    float2 acc = make_float2(0.f, 0.f);
#pragma unroll 8
    for (int s = 0; s < 64; s++) {
        const float2 e2 = *(const float2*)&ebase[(size_t)s * DIM];
        const float w = aws[s];
        acc.x = fmaf(w, e2.x, acc.x);
        acc.y = fmaf(w, e2.y, acc.y);
    }
    *(float2*)&g_cpart[(q * BATCH + b) * DIM + d] = acc;
}
__global__ void context_sum_kernel(float* __restrict__ outc) {
    const int i = blockIdx.x * 256 + threadIdx.x;
    const int N = BATCH * DIM;
    float s0 = g_cpart[i]         + g_cpart[N + i];
    float s1 = g_cpart[2 * N + i] + g_cpart[3 * N + i];
    float s2 = g_cpart[4 * N + i] + g_cpart[5 * N + i];
    float s3 = g_cpart[6 * N + i] + g_cpart[7 * N + i];
    outc[i] = (s0 + s1) + (s2 + s3);
}

// ---------------------------------------------------------------------------
extern "C" void kernel_launch(void* const* d_in, const int* in_sizes, int n_in,
                              void* d_out, int out_size) {
    const float* h_dec = (const float*)d_in[0];
    const float* c_dec = (const float*)d_in[1];
    const float* enc   = (const float*)d_in[2];
    const float* mask  = (const float*)d_in[3];
    const float* cov   = (const float*)d_in[4];
    const float* Wh    = (const float*)d_in[5];
    const float* Ws    = (const float*)d_in[6];
    const float* Wsb   = (const float*)d_in[7];
    const float* v     = (const float*)d_in[8];
    const float* wc    = (const float*)d_in[9];
    float* out = (float*)d_out;

    // Which variant did the runtime load? tc path has no static smem;
    // fallback carries 16KB static As/Bs.
    cudaFuncAttributes fa;
    cudaFuncGetAttributes(&fa, score_kernel);
    const bool tc = (fa.sharedSizeBytes < 8192);
    size_t dyn = 0;
    if (tc) {
        cudaFuncSetAttribute(score_kernel,
                             cudaFuncAttributeMaxDynamicSharedMemorySize, SMEM_DYN);
        dyn = SMEM_DYN;
        convB_kernel<<<dim3(32, 2), 256>>>(Wh);
    }
    dec_feat_kernel<<<dim3(8, 32), 128>>>(h_dec, c_dec, Ws, Wsb);
    score_kernel<<<MROWS / 128, 256, dyn>>>(enc, Wh, cov, v, wc);
    softmax_kernel<<<BATCH, SEQ>>>(mask, cov, out);
    context_part_kernel<<<dim3(8, BATCH), 512>>>(enc, out + BATCH * DIM);
    context_sum_kernel<<<BATCH * DIM / 256, 256>>>(out);
}